// round 15
// baseline (speedup 1.0000x reference)
#include <cuda_runtime.h>
#include <cuda_fp16.h>
#include <cstdint>

#define NV      50000
#define BM      128
#define NVT     ((NV + BM - 1) / BM)   // 391
#define CHUNKS  41
#define A_STRIDE_H 72                  // halves per vertex row (pad vs 64)

// SMEM byte offsets
#define SM_A0    0
#define SM_A1    18432                 // 128*72*2
#define SM_BIAS  36864
#define SMEM_TOTAL 37120

// Folded weights, fp16, fragment-major, chunk-blocked, B-paired:
// [nt(2)][chunk(41)][w4(4)][pair(4)][ks(4)][lane(32)][inp(2)][reg(2)][half(2)]
// -> 2.625 MB (L2-resident; each thread's fragment pair = contiguous 16B)
__device__ __align__(256) __half g_W[2u * 41 * 16384];

// Mesh signal pre-converted to fp16: 50000 x 64 = 6.4 MB
__device__ __align__(256) __half g_mesh[NV * 64];

// ---------------------------------------------------------------------------
// helpers
// ---------------------------------------------------------------------------
__device__ __forceinline__ uint32_t smem_u32(const void* p) {
    uint32_t a;
    asm("{ .reg .u64 t; cvta.to.shared.u64 t, %1; cvt.u32.u64 %0, t; }"
        : "=r"(a) : "l"(p));
    return a;
}
__device__ __forceinline__ void ldmA(unsigned* r, uint32_t addr) {
    asm volatile("ldmatrix.sync.aligned.m8n8.x4.shared.b16 {%0,%1,%2,%3}, [%4];"
                 : "=r"(r[0]), "=r"(r[1]), "=r"(r[2]), "=r"(r[3]) : "r"(addr));
}
__device__ __forceinline__ void mma16(float* d, const unsigned* a, const unsigned* b) {
    asm volatile(
        "mma.sync.aligned.m16n8k16.row.col.f32.f16.f16.f32 "
        "{%0,%1,%2,%3}, {%4,%5,%6,%7}, {%8,%9}, {%0,%1,%2,%3};"
        : "+f"(d[0]), "+f"(d[1]), "+f"(d[2]), "+f"(d[3])
        : "r"(a[0]), "r"(a[1]), "r"(a[2]), "r"(a[3]), "r"(b[0]), "r"(b[1]));
}

// ---------------------------------------------------------------------------
// Mesh fp16 conversion: g_mesh[i] = half(mesh[i])
// ---------------------------------------------------------------------------
__global__ void mesh_half_kernel(const float* __restrict__ mesh) {
    const int i = (blockIdx.x * blockDim.x + threadIdx.x) * 4;
    if (i < NV * 64) {
        const float4 v = *(const float4*)(mesh + i);
        const __half2 h0 = __floats2half2_rn(v.x, v.y);
        const __half2 h1 = __floats2half2_rn(v.z, v.w);
        uint2 u;
        u.x = *(const unsigned*)&h0;
        u.y = *(const unsigned*)&h1;
        *(uint2*)(&g_mesh[i]) = u;
    }
}

// ---------------------------------------------------------------------------
// Fold kernel: W'[k=(m,c)][n=(o,t)] = sum_{r2,a2} coeff[r2,a2,m] * nw[t,r2,(a2+o)&7,c]
// (m=40 -> center row = cw[t][c], replicated over o). Written fp16,
// fragment-major per the g_W layout above (m16n8k16 B-fragments, paired).
// ---------------------------------------------------------------------------
__global__ void fold_kernel(const float* __restrict__ nw,
                            const float* __restrict__ cw,
                            const float* __restrict__ coeff) {
    const int m = blockIdx.x;    // 0..40
    const int t = blockIdx.y;    // 0..63
    const int c = threadIdx.x;   // 0..63

    float vals[8];
    if (m < 40) {
        float nwreg[40], coreg[40];
#pragma unroll
        for (int ra = 0; ra < 40; ra++)
            nwreg[ra] = nw[(t * 40 + ra) * 64 + c];
#pragma unroll
        for (int ra = 0; ra < 40; ra++)
            coreg[ra] = coeff[ra * 40 + m];
#pragma unroll
        for (int o = 0; o < 8; o++) {
            float acc = 0.f;
#pragma unroll
            for (int r = 0; r < 5; r++)
#pragma unroll
                for (int a = 0; a < 8; a++)
                    acc = fmaf(coreg[r * 8 + a], nwreg[r * 8 + ((a + o) & 7)], acc);
            vals[o] = acc;
        }
    } else {
        const float vv = cw[t * 64 + c];
#pragma unroll
        for (int o = 0; o < 8; o++) vals[o] = vv;
    }

    // m16n8k16 B-fragment coords for k index c (0..63):
    const int ks   = c >> 4;          // k16 step
    const int kk   = c & 15;          // k within step
    const int reg  = kk >> 3;         // b0: k0-7, b1: k8-15
    const int half = kk & 1;
    const int tin  = (kk & 7) >> 1;   // tid_in_group
#pragma unroll
    for (int o = 0; o < 8; o++) {
        const int n    = o * 64 + t;
        const int nt   = n >> 8;
        const int nn   = n & 255;
        const int w4   = nn >> 6;
        const int tt   = (nn >> 3) & 7;
        const int pair = tt >> 1, inp = tt & 1;
        const int lane = (n & 7) * 4 + tin;
        const size_t idx =
            ((((((size_t)(nt * 41 + m) * 4 + w4) * 4 + pair) * 4 + ks) * 32 + lane) * 8)
            + inp * 4 + reg * 2 + half;
        g_W[idx] = __float2half_rn(vals[o]);
    }
}

// ---------------------------------------------------------------------------
// A-tile builder: fp16 mesh gather + fp32 interp + fp16 store into As[v][c].
// 2 threads per vertex, each handles 32 contiguous channels (4x LDG.128/row).
// ---------------------------------------------------------------------------
__device__ __forceinline__ void build_a(char* abase, int chunk, int v, int c0,
                                        int vcl, float2 p0, float2 p1, float2 p2) {
    float w0, w1, w2;
    const uint4 *r0, *r1, *r2;
    if (chunk < 40) {
        w0 = p0.y; w1 = p1.y; w2 = p2.y;
        r0 = (const uint4*)(g_mesh + (size_t)(int)p0.x * 64 + c0);
        r1 = (const uint4*)(g_mesh + (size_t)(int)p1.x * 64 + c0);
        r2 = (const uint4*)(g_mesh + (size_t)(int)p2.x * 64 + c0);
    } else {  // center: raw mesh row
        w0 = 1.f; w1 = 0.f; w2 = 0.f;
        r0 = r1 = r2 = (const uint4*)(g_mesh + (size_t)vcl * 64 + c0);
    }
    char* dst = abase + (v * A_STRIDE_H + c0) * 2;
#pragma unroll
    for (int j = 0; j < 4; j++) {          // 4 x 8 halves per row
        const uint4 a0 = r0[j], a1 = r1[j], a2 = r2[j];
        const unsigned* u0 = (const unsigned*)&a0;
        const unsigned* u1 = (const unsigned*)&a1;
        const unsigned* u2 = (const unsigned*)&a2;
        unsigned res[4];
#pragma unroll
        for (int q = 0; q < 4; q++) {
            const float2 f0 = __half22float2(*(const __half2*)&u0[q]);
            const float2 f1 = __half22float2(*(const __half2*)&u1[q]);
            const float2 f2 = __half22float2(*(const __half2*)&u2[q]);
            const float rx = fmaf(w0, f0.x, fmaf(w1, f1.x, w2 * f2.x));
            const float ry = fmaf(w0, f0.y, fmaf(w1, f1.y, w2 * f2.y));
            const __half2 h = __floats2half2_rn(rx, ry);
            res[q] = *(const unsigned*)&h;
        }
        *(uint4*)(dst + j * 16) = make_uint4(res[0], res[1], res[2], res[3]);
    }
}

// ---------------------------------------------------------------------------
// Main kernel: 256 threads, 8 warps (2 M-rows x 4 N-cols), warp tile 64x32.
// CTA tile 128x128, 2 CTAs/SM for cross-CTA latency hiding.
// fp16 m16n8k16, ldmatrix.x4 A; B streamed from L2 via LDG.128, 1-step ahead.
// ---------------------------------------------------------------------------
__global__ __launch_bounds__(256, 2)
void conv_mma_kernel(const float* __restrict__ bary,
                     const float* __restrict__ bias,
                     float* __restrict__ out) {
    extern __shared__ __align__(128) char smem[];
    const uint32_t sbase = smem_u32(smem);

    const int tid  = threadIdx.x;
    const int lane = tid & 31;
    const int wid  = tid >> 5;           // 0..7
    const int wm   = wid >> 2;           // 0..1
    const int wn2  = wid & 3;            // 0..3  (32-col groups within 128)
    const int nq   = blockIdx.x;         // 0..3  (128-col quarter of 512)
    const int nt   = nq >> 1;            // g_W nt block
    const int w4   = ((nq & 1) << 1) | (wn2 >> 1);   // 64-col group in nt block
    const int thal = (wn2 & 1) * 4;      // tt offset within the 64-col group
    const int ppair = thal >> 1;         // 0 or 2 : first pair index
    const int vt   = blockIdx.y;         // 0..390

    if (tid < 64) ((float*)(smem + SM_BIAS))[tid] = bias[tid];

    // Per-warp B base in gmem (fragment-major; lane offset folded in)
    const char* gWb = (const char*)g_W + (size_t)nt * 41 * 32768
                      + w4 * 8192 + lane * 16;

    const int v   = tid >> 1;            // 0..127 (local vertex)
    const int c0  = (tid & 1) * 32;      // channel half
    const int vg  = vt * BM + v;
    const int vcl = vg < NV ? vg : NV - 1;
    const float* bary_v = bary + (size_t)vcl * 240;   // 40*3*2

    // ldmatrix per-lane address: lanes 0-7 m0 (rows 0-7, k0-7), 8-15 m1 (rows
    // 8-15), 16-23 m2 (rows 0-7, k8-15: +16B), 24-31 m3.
    const int lrow = lane & 15;
    const int lch  = lane >> 4;
    const uint32_t aoff = (uint32_t)((wm * 64 + lrow) * (A_STRIDE_H * 2) + lch * 16);

    float acc[4][4][4];
#pragma unroll
    for (int mt = 0; mt < 4; mt++)
#pragma unroll
        for (int t = 0; t < 4; t++)
#pragma unroll
            for (int q = 0; q < 4; q++) acc[mt][t][q] = 0.f;

    // ---------------- prologue: stage 0 ----------------
    uint4 bc0, bc1;   // current-ks B fragments (pair 0, pair 1)
    {
        bc0 = *(const uint4*)(gWb + ((ppair + 0) * 4 + 0) * 512);
        bc1 = *(const uint4*)(gWb + ((ppair + 1) * 4 + 0) * 512);
        const float2 p0 = *(const float2*)(bary_v + 0);
        const float2 p1 = *(const float2*)(bary_v + 2);
        const float2 p2 = *(const float2*)(bary_v + 4);
        build_a(smem + SM_A0, 0, v, c0, vcl, p0, p1, p2);
        __syncthreads();
    }

    // ---------------- main loop ----------------
    for (int c = 0; c < CHUNKS; c++) {
        const int s   = c & 1;
        const int ncn = c + 1;
        float2 p0 = make_float2(0.f, 0.f), p1 = p0, p2 = p0;

        if (ncn < 40) {   // prefetch bary for next chunk
            p0 = *(const float2*)(bary_v + ncn * 6 + 0);
            p1 = *(const float2*)(bary_v + ncn * 6 + 2);
            p2 = *(const float2*)(bary_v + ncn * 6 + 4);
        }

        // ---- mma over A buffer s; B streams from L2 one ks ahead ----
        const uint32_t Aaddr = sbase + (s ? SM_A1 : SM_A0) + aoff;
#pragma unroll
        for (int ks = 0; ks < 4; ks++) {
            // issue next-step B loads (ks+1, or next chunk's ks=0)
            const int nc = (ks < 3) ? c : (c < 40 ? c + 1 : c);
            const int nk = (ks + 1) & 3;
            const char* nb = gWb + (size_t)nc * 32768;
            const uint4 bn0 = *(const uint4*)(nb + ((ppair + 0) * 4 + nk) * 512);
            const uint4 bn1 = *(const uint4*)(nb + ((ppair + 1) * 4 + nk) * 512);

            unsigned af[4][4];
#pragma unroll
            for (int mt = 0; mt < 4; mt++)
                ldmA(af[mt], Aaddr + (uint32_t)(mt * 16 * A_STRIDE_H * 2 + ks * 32));

            unsigned bf[4][2];
            bf[0][0] = bc0.x; bf[0][1] = bc0.y;
            bf[1][0] = bc0.z; bf[1][1] = bc0.w;
            bf[2][0] = bc1.x; bf[2][1] = bc1.y;
            bf[3][0] = bc1.z; bf[3][1] = bc1.w;
#pragma unroll
            for (int mt = 0; mt < 4; mt++)
#pragma unroll
                for (int t = 0; t < 4; t++)
                    mma16(acc[mt][t], af[mt], bf[t]);

            bc0 = bn0; bc1 = bn1;
        }

        // ---- build next A into buffer s^1 ----
        if (ncn < CHUNKS)
            build_a(smem + (s ? SM_A0 : SM_A1), ncn, v, c0, vcl, p0, p1, p2);

        __syncthreads();
    }

    // ---------------- epilogue: +bias, relu, store ----------------
    const float* sbias = (const float*)(smem + SM_BIAS);
#pragma unroll
    for (int mt = 0; mt < 4; mt++) {
        const int row0 = vt * BM + wm * 64 + mt * 16 + (lane >> 2);
        const int row1 = row0 + 8;
#pragma unroll
        for (int t = 0; t < 4; t++) {
            const int cloc = (thal + t) * 8 + (lane & 3) * 2;  // 0..63 within group
            const int col  = nt * 256 + w4 * 64 + cloc;
            const float b0 = sbias[cloc];
            const float b1 = sbias[cloc + 1];
            if (row0 < NV) {
                float2 o0;
                o0.x = fmaxf(acc[mt][t][0] + b0, 0.f);
                o0.y = fmaxf(acc[mt][t][1] + b1, 0.f);
                *(float2*)(out + (size_t)row0 * 512 + col) = o0;
            }
            if (row1 < NV) {
                float2 o1;
                o1.x = fmaxf(acc[mt][t][2] + b0, 0.f);
                o1.y = fmaxf(acc[mt][t][3] + b1, 0.f);
                *(float2*)(out + (size_t)row1 * 512 + col) = o1;
            }
        }
    }
}

extern "C" void kernel_launch(void* const* d_in, const int* in_sizes, int n_in,
                              void* d_out, int out_size) {
    const float* mesh  = (const float*)d_in[0];  // (50000, 64)
    const float* bary  = (const float*)d_in[1];  // (50000, 5, 8, 3, 2)
    const float* nw    = (const float*)d_in[2];  // (64, 5, 8, 64)
    const float* cw    = (const float*)d_in[3];  // (64, 1, 64)
    const float* bias  = (const float*)d_in[4];  // (64,)
    const float* coeff = (const float*)d_in[5];  // (5, 8, 40)
    float* out = (float*)d_out;                  // (50000, 8, 64)

    static int smem_set = 0;
    if (!smem_set) {
        cudaFuncSetAttribute(conv_mma_kernel,
                             cudaFuncAttributeMaxDynamicSharedMemorySize, SMEM_TOTAL);
        smem_set = 1;
    }

    mesh_half_kernel<<<(NV * 64 / 4 + 255) / 256, 256>>>(mesh);
    fold_kernel<<<dim3(41, 64), 64>>>(nw, cw, coeff);
    conv_mma_kernel<<<dim3(4, NVT), 256, SMEM_TOTAL>>>(bary, bias, out);
}